// round 11
// baseline (speedup 1.0000x reference)
#include <cuda_runtime.h>

#define HH   112
#define WWD  112
#define HW   12544
#define CIN  128
#define CO   64
#define BATCH 2

// parity-space constants: K=7, D=1, L=56
#define PL   56
#define PT   8          // parity tile = 8x8
#define HALO 14         // 8 + 6
#define PAD  68         // floats per loc -> 17 float4 slots
#define HALO_MAX (HALO * HALO)   // 196

// GEMM smem layout (floats, dynamic)
// Ws: [m][c][o] resident, c=0..127, stride 68  -> 3 * 128 * 68 = 26112 floats
// Xs0/Xs1: [c][px] 32x128 ping-pong            -> 2 * 4096 floats
// Wst staging (one-time) aliases the X buffers  (needs 6336 <= 8192)
#define WS_STRIDE 68
#define WS_MAT    (128 * WS_STRIDE)    // 8704
#define WST_STRIDE 33
#define WST_MAT    (64 * WST_STRIDE)   // 2112
#define OFF_WS   0
#define OFF_XS0  (3 * WS_MAT)                  // 26112
#define OFF_XS1  (OFF_XS0 + 4096)              // 30208
#define GEMM_SMEM_FLOATS (OFF_XS1 + 4096)      // 34304 -> 137216 B

typedef unsigned long long ull;

// scratch
__device__ __align__(128) float g_q[BATCH * HW * CO];
__device__ __align__(128) float g_k[BATCH * HW * CO];
__device__ __align__(128) float g_v[BATCH * HW * CO];

// ---------------------------------------------------------------------------
__device__ __forceinline__ ull pk2(float x, float y) {
    ull r; asm("mov.b64 %0, {%1,%2};" : "=l"(r) : "f"(x), "f"(y)); return r;
}
__device__ __forceinline__ void upk2(ull v, float& x, float& y) {
    asm("mov.b64 {%0,%1}, %2;" : "=f"(x), "=f"(y) : "l"(v));
}
__device__ __forceinline__ void fma2(ull& d, ull a, ull b) {
    asm("fma.rn.f32x2 %0, %1, %2, %3;" : "=l"(d) : "l"(a), "l"(b), "l"(d));
}

// ---------------------------------------------------------------------------
// Fused QKV GEMM, resident transposed W + double-buffered X.
// Tile 128 px x 64 out x 3 mats, 512 threads, 4 px x 4 out per thread.
// One-time W transpose (4 staged passes, all bank-clean), then per chunk:
// issue X LDGs for c+1, compute 32 kk on buffer c, STS, ONE sync.
// ---------------------------------------------------------------------------
__global__ __launch_bounds__(512) void qkv_gemm(
    const float* __restrict__ x,
    const float* __restrict__ Wq, const float* __restrict__ Wk,
    const float* __restrict__ Wv,
    const float* __restrict__ bq, const float* __restrict__ bk,
    const float* __restrict__ bv)
{
    extern __shared__ float sm[];
    float* Ws  = sm + OFF_WS;
    float* Xs0 = sm + OFF_XS0;
    float* Xs1 = sm + OFF_XS1;
    float* Wst = Xs0;                      // one-time staging alias

    const int b   = blockIdx.y;
    const int hw0 = blockIdx.x * 128;
    const int tid = threadIdx.x;
    const int tp  = tid >> 4;              // 0..31 (4 px each)
    const int to  = tid & 15;              // 0..15 (4 out each)

    const float* xb = x + (size_t)b * CIN * HW + hw0;
    const float* Wsrc[3] = { Wq, Wk, Wv };

    // ---- one-time W transpose: W[o][c] -> Ws[m][c][o] (stride 68) ----
    {
        const int m_  = tid >> 9;          // always 0 (512 thr), decode per t
        (void)m_;
#pragma unroll
        for (int s = 0; s < 4; s++) {
            // stage A: coalesced LDG rows -> Wst stride 33 (banks o+4j4+i distinct)
#pragma unroll
            for (int t = 0; t < 3; t++) {
                int idx = tid + t * 512;   // 0..1535
                int m   = idx >> 9;
                int rem = idx & 511;
                int o   = rem >> 3;        // 0..63
                int j4  = rem & 7;         // 0..7
                float4 wv = *(const float4*)(Wsrc[m] + (size_t)o * CIN + 32 * s + j4 * 4);
                float* dst = Wst + m * WST_MAT + o * WST_STRIDE + j4 * 4;
                dst[0] = wv.x; dst[1] = wv.y; dst[2] = wv.z; dst[3] = wv.w;
            }
            __syncthreads();
            // stage B: gather columns (LDS banks 4o4+i+kk distinct),
            // STS.128 into Ws rows (slots 17*kk + o4, phase-clean)
#pragma unroll
            for (int t = 0; t < 3; t++) {
                int idx = tid + t * 512;
                int m   = idx >> 9;
                int rem = idx & 511;
                int o4  = rem >> 5;        // 0..15
                int kk  = rem & 31;        // 0..31
                const float* src = Wst + m * WST_MAT + kk;
                float4 v;
                v.x = src[(o4 * 4 + 0) * WST_STRIDE];
                v.y = src[(o4 * 4 + 1) * WST_STRIDE];
                v.z = src[(o4 * 4 + 2) * WST_STRIDE];
                v.w = src[(o4 * 4 + 3) * WST_STRIDE];
                *(float4*)(Ws + m * WS_MAT + (32 * s + kk) * WS_STRIDE + o4 * 4) = v;
            }
            __syncthreads();
        }
    }

    // decode X-load indices once (2 float4 per thread per chunk)
    int xc[2], xp[2];
#pragma unroll
    for (int t = 0; t < 2; t++) {
        int idx = tid + t * 512;
        xc[t] = idx >> 5;                  // channel 0..31
        xp[t] = idx & 31;                  // px-float4 0..31
    }

    // load X chunk 0 into Xs0
#pragma unroll
    for (int t = 0; t < 2; t++)
        ((float4*)Xs0)[xc[t] * 32 + xp[t]] =
            *(const float4*)(xb + (size_t)xc[t] * HW + xp[t] * 4);
    __syncthreads();

    ull acc[3][4][2];
#pragma unroll
    for (int m = 0; m < 3; m++)
#pragma unroll
        for (int i = 0; i < 4; i++)
#pragma unroll
            for (int j = 0; j < 2; j++) acc[m][i][j] = 0ull;

#pragma unroll
    for (int c = 0; c < 4; c++) {
        float* Xc = (c & 1) ? Xs1 : Xs0;
        float* Xn = (c & 1) ? Xs0 : Xs1;

        // issue next-chunk LDGs early; data consumed after compute
        float4 xr[2];
        if (c < 3) {
            const int kc = 32 * (c + 1);
#pragma unroll
            for (int t = 0; t < 2; t++)
                xr[t] = *(const float4*)(xb + (size_t)(kc + xc[t]) * HW + xp[t] * 4);
        }

        const float* Wc = Ws + 32 * c * WS_STRIDE;
#pragma unroll 4
        for (int kk = 0; kk < 32; kk++) {
            float4 af = *(const float4*)(Xc + kk * 128 + tp * 4);
            ull a0 = pk2(af.x, af.x), a1 = pk2(af.y, af.y);
            ull a2_ = pk2(af.z, af.z), a3 = pk2(af.w, af.w);
#pragma unroll
            for (int m = 0; m < 3; m++) {
                ulonglong2 w2 = *(const ulonglong2*)(Wc + m * WS_MAT + kk * WS_STRIDE + to * 4);
                fma2(acc[m][0][0], a0, w2.x);  fma2(acc[m][0][1], a0, w2.y);
                fma2(acc[m][1][0], a1, w2.x);  fma2(acc[m][1][1], a1, w2.y);
                fma2(acc[m][2][0], a2_, w2.x); fma2(acc[m][2][1], a2_, w2.y);
                fma2(acc[m][3][0], a3, w2.x);  fma2(acc[m][3][1], a3, w2.y);
            }
        }

        if (c < 3) {
#pragma unroll
            for (int t = 0; t < 2; t++)
                ((float4*)Xn)[xc[t] * 32 + xp[t]] = xr[t];
            __syncthreads();
        }
    }

    // epilogue: + bias, * scale, store (b, hw, o) with o contiguous
    const float* biases[3] = { bq, bk, bv };
    float* outs[3] = { g_q, g_k, g_v };
    const float scales[3] = { 0.125f, 1.0f, 1.0f };
#pragma unroll
    for (int m = 0; m < 3; m++) {
        float4 bs = *(const float4*)(biases[m] + to * 4);
        float s = scales[m];
        float* ob = outs[m] + ((size_t)b * HW + hw0 + tp * 4) * CO + to * 4;
#pragma unroll
        for (int i = 0; i < 4; i++) {
            float r0, r1, r2, r3;
            upk2(acc[m][i][0], r0, r1);
            upk2(acc[m][i][1], r2, r3);
            float4 v = make_float4((r0 + bs.x) * s, (r1 + bs.y) * s,
                                   (r2 + bs.z) * s, (r3 + bs.w) * s);
            *(float4*)(ob + (size_t)i * CO) = v;
        }
    }
}

// ---------------------------------------------------------------------------
// Fused neighborhood attention — UNCHANGED from R10 (measured 32.2us).
// ---------------------------------------------------------------------------
__global__ __launch_bounds__(256, 2) void natt_kernel(float* __restrict__ outp)
{
    extern __shared__ float sm[];
    float* Ks = sm;
    float* Vs = sm + HALO_MAX * PAD;

    const int z    = blockIdx.z;
    const int b    = z >> 2;
    const int parh = (z >> 1) & 1;
    const int parw = z & 1;
    const int ph0  = blockIdx.y * PT;
    const int pw0  = blockIdx.x * PT;
    const int r0p  = max(0, ph0 - 3);
    const int c0p  = max(0, pw0 - 3);
    const int rows = min(HALO, PL - r0p);
    const int cols = min(HALO, PL - c0p);
    const int tid  = threadIdx.x;

    // halo load: 16 threads per loc, float4 each
    {
        const float* kb = g_k + (size_t)b * HW * CO;
        const float* vb = g_v + (size_t)b * HW * CO;
        const int l16 = tid & 15;
        const int nloc = rows * cols;
        for (int loc = tid >> 4; loc < nloc; loc += 16) {
            int lr = loc / cols;
            int lc = loc - lr * cols;
            int h  = 2 * (r0p + lr) + parh;
            int w  = 2 * (c0p + lc) + parw;
            size_t g = ((size_t)h * WWD + w) * CO + l16 * 4;
            int s = loc * PAD + l16 * 4;
            *(float4*)(Ks + s) = *(const float4*)(kb + g);
            *(float4*)(Vs + s) = *(const float4*)(vb + g);
        }
    }
    __syncthreads();

    const int lane = tid & 31;
    const int warp = tid >> 5;        // tile row 0..7
    const int sub  = lane >> 3;       // channel quarter 0..3
    const int pwl  = lane & 7;        // tile col 0..7
    const int ph   = ph0 + warp;
    const int pw   = pw0 + pwl;
    const int h    = 2 * ph + parh;
    const int w    = 2 * pw + parw;

    const float* qp = g_q + ((size_t)b * HW + (size_t)h * WWD + w) * CO + sub * 16;
    ulonglong2 qa = *(const ulonglong2*)(qp);
    ulonglong2 qb_ = *(const ulonglong2*)(qp + 4);
    ulonglong2 qc = *(const ulonglong2*)(qp + 8);
    ulonglong2 qd = *(const ulonglong2*)(qp + 12);
    ull qq[8] = { qa.x, qa.y, qb_.x, qb_.y, qc.x, qc.y, qd.x, qd.y };

    const int wsh = min(max(ph - 3, 0), PL - 7);
    const int wsw = min(max(pw - 3, 0), PL - 7);
    const int rowstride = cols * PAD;
    int rb[7], cb[7];
#pragma unroll
    for (int j = 0; j < 7; j++) {
        rb[j] = (wsh + j - r0p) * rowstride + sub * 16;
        cb[j] = (wsw + j - c0p) * PAD;
    }

    float sc[49];
#pragma unroll
    for (int jh = 0; jh < 7; jh++) {
#pragma unroll
        for (int jw = 0; jw < 7; jw++) {
            const float* kp = Ks + rb[jh] + cb[jw];
            ull s2a = 0ull, s2b = 0ull;
#pragma unroll
            for (int i = 0; i < 4; i++) {
                ulonglong2 kv = *(const ulonglong2*)(kp + i * 4);
                fma2(s2a, qq[2 * i],     kv.x);
                fma2(s2b, qq[2 * i + 1], kv.y);
            }
            float ax, ay, bx, by;
            upk2(s2a, ax, ay);
            upk2(s2b, bx, by);
            float s = (ax + bx) + (ay + by);
            s += __shfl_xor_sync(0xffffffffu, s, 8);
            s += __shfl_xor_sync(0xffffffffu, s, 16);
            sc[jh * 7 + jw] = s;
        }
    }

    float m = sc[0];
#pragma unroll
    for (int j = 1; j < 49; j++) m = fmaxf(m, sc[j]);
    float sum = 0.f;
#pragma unroll
    for (int j = 0; j < 49; j++) { sc[j] = __expf(sc[j] - m); sum += sc[j]; }
    const float inv = 1.0f / sum;

    ull a2[8];
#pragma unroll
    for (int i = 0; i < 8; i++) a2[i] = 0ull;
#pragma unroll
    for (int jh = 0; jh < 7; jh++) {
#pragma unroll
        for (int jw = 0; jw < 7; jw++) {
            float pj = sc[jh * 7 + jw] * inv;
            ull pp = pk2(pj, pj);
            const float* vp = Vs + rb[jh] + cb[jw];
#pragma unroll
            for (int i = 0; i < 4; i++) {
                ulonglong2 vv = *(const ulonglong2*)(vp + i * 4);
                fma2(a2[2 * i],     pp, vv.x);
                fma2(a2[2 * i + 1], pp, vv.y);
            }
        }
    }

    float* ob = outp + ((size_t)b * CO + sub * 16) * HW + (size_t)h * WWD + w;
#pragma unroll
    for (int i = 0; i < 8; i++) {
        float x0, x1;
        upk2(a2[i], x0, x1);
        ob[(size_t)(2 * i) * HW]     = x0;
        ob[(size_t)(2 * i + 1) * HW] = x1;
    }
}

// ---------------------------------------------------------------------------
extern "C" void kernel_launch(void* const* d_in, const int* in_sizes, int n_in,
                              void* d_out, int out_size)
{
    (void)in_sizes; (void)n_in; (void)out_size;
    const float* x  = (const float*)d_in[0];
    const float* Wq = (const float*)d_in[1];
    const float* bq = (const float*)d_in[2];
    const float* Wk = (const float*)d_in[3];
    const float* bk = (const float*)d_in[4];
    const float* Wv = (const float*)d_in[5];
    const float* bv = (const float*)d_in[6];
    float* out = (float*)d_out;

    const int gsmem = GEMM_SMEM_FLOATS * (int)sizeof(float);    // 137216
    cudaFuncSetAttribute(qkv_gemm, cudaFuncAttributeMaxDynamicSharedMemorySize, gsmem);
    qkv_gemm<<<dim3(98, 2), 512, gsmem>>>(x, Wq, Wk, Wv, bq, bk, bv);

    const int smem = 2 * HALO_MAX * PAD * (int)sizeof(float);   // 106624
    cudaFuncSetAttribute(natt_kernel, cudaFuncAttributeMaxDynamicSharedMemorySize, smem);
    natt_kernel<<<dim3(7, 7, 8), 256, smem>>>(out);
}

// round 12
// speedup vs baseline: 1.0288x; 1.0288x over previous
#include <cuda_runtime.h>

#define HH   112
#define WWD  112
#define HW   12544
#define CIN  128
#define CO   64
#define BATCH 2

// parity-space constants: K=7, D=1, L=56
#define PL   56
#define PT   8          // parity tile = 8x8
#define HALO 14         // 8 + 6
#define PAD  68         // floats per loc -> 17 float4 slots
#define HALO_MAX (HALO * HALO)   // 196

typedef unsigned long long ull;

// scratch
__device__ __align__(128) float g_q[BATCH * HW * CO];
__device__ __align__(128) float g_k[BATCH * HW * CO];
__device__ __align__(128) float g_v[BATCH * HW * CO];
__device__ __align__(128) float g_Wt[3 * CIN * CO];   // [m][c][o]

// ---------------------------------------------------------------------------
__device__ __forceinline__ ull pk2(float x, float y) {
    ull r; asm("mov.b64 %0, {%1,%2};" : "=l"(r) : "f"(x), "f"(y)); return r;
}
__device__ __forceinline__ void upk2(ull v, float& x, float& y) {
    asm("mov.b64 {%0,%1}, %2;" : "=f"(x), "=f"(y) : "l"(v));
}
__device__ __forceinline__ void fma2(ull& d, ull a, ull b) {
    asm("fma.rn.f32x2 %0, %1, %2, %3;" : "=l"(d) : "l"(a), "l"(b), "l"(d));
}

// ---------------------------------------------------------------------------
// One-shot W transpose: g_Wt[m][c][o] = Wm[o][c]. (measured 4.4us)
// ---------------------------------------------------------------------------
__global__ void transposeW(const float* __restrict__ Wq,
                           const float* __restrict__ Wk,
                           const float* __restrict__ Wv)
{
    int idx = blockIdx.x * 256 + threadIdx.x;      // 0..24575
    int m   = idx >> 13;
    int rem = idx & 8191;
    int o   = rem >> 7;
    int c   = rem & 127;
    const float* W = (m == 0) ? Wq : (m == 1) ? Wk : Wv;
    g_Wt[m * 8192 + c * 64 + o] = W[o * 128 + c];
}

// ---------------------------------------------------------------------------
// Fused QKV GEMM — gemm_A: g_Wt smem path, 2 syncs/chunk, out-pair f32x2
// packing. This exact structure measured ~20us inside the R6/R8 runs.
// Tile 128 px x 64 out x 3 mats, 512 threads, 4 px x 4 out per thread.
// ---------------------------------------------------------------------------
__global__ __launch_bounds__(512) void qkv_gemm(
    const float* __restrict__ x,
    const float* __restrict__ bq, const float* __restrict__ bk,
    const float* __restrict__ bv)
{
    __shared__ float Xs[32 * 128];        // [c][px] 16KB
    __shared__ float Ws[3 * 32 * 64];     // [m][c][o] 24KB

    const int b   = blockIdx.y;
    const int hw0 = blockIdx.x * 128;
    const int tid = threadIdx.x;
    const int tp  = tid >> 4;             // 0..31 (4 px each)
    const int to  = tid & 15;             // 0..15 (4 out each)

    ull acc[3][4][2];
#pragma unroll
    for (int m = 0; m < 3; m++)
#pragma unroll
        for (int i = 0; i < 4; i++)
#pragma unroll
            for (int j = 0; j < 2; j++) acc[m][i][j] = 0ull;

    const float* xb = x + (size_t)b * CIN * HW + hw0;

    for (int kc = 0; kc < CIN; kc += 32) {
        __syncthreads();
#pragma unroll
        for (int t = 0; t < 2; t++) {
            int idx = tid + t * 512;
            int c   = idx >> 5;
            int p4  = idx & 31;
            ((float4*)Xs)[c * 32 + p4] =
                *(const float4*)(xb + (size_t)(kc + c) * HW + p4 * 4);
        }
#pragma unroll
        for (int t = 0; t < 3; t++) {
            int idx = tid + t * 512;
            int m   = idx >> 9;
            int rem = idx & 511;
            int kk  = rem >> 4;
            int o4  = rem & 15;
            ((float4*)Ws)[idx] =
                *(const float4*)(g_Wt + m * 8192 + (kc + kk) * 64 + o4 * 4);
        }
        __syncthreads();

#pragma unroll 4
        for (int kk = 0; kk < 32; kk++) {
            float4 af = *(const float4*)(Xs + kk * 128 + tp * 4);
            ull a0 = pk2(af.x, af.x), a1 = pk2(af.y, af.y);
            ull a2_ = pk2(af.z, af.z), a3 = pk2(af.w, af.w);
#pragma unroll
            for (int m = 0; m < 3; m++) {
                ulonglong2 w2 = *(const ulonglong2*)(Ws + m * 2048 + kk * 64 + to * 4);
                fma2(acc[m][0][0], a0, w2.x);  fma2(acc[m][0][1], a0, w2.y);
                fma2(acc[m][1][0], a1, w2.x);  fma2(acc[m][1][1], a1, w2.y);
                fma2(acc[m][2][0], a2_, w2.x); fma2(acc[m][2][1], a2_, w2.y);
                fma2(acc[m][3][0], a3, w2.x);  fma2(acc[m][3][1], a3, w2.y);
            }
        }
    }

    const float* biases[3] = { bq, bk, bv };
    float* outs[3] = { g_q, g_k, g_v };
    const float scales[3] = { 0.125f, 1.0f, 1.0f };
#pragma unroll
    for (int m = 0; m < 3; m++) {
        float4 bs = *(const float4*)(biases[m] + to * 4);
        float s = scales[m];
        float* ob = outs[m] + ((size_t)b * HW + hw0 + tp * 4) * CO + to * 4;
#pragma unroll
        for (int i = 0; i < 4; i++) {
            float r0, r1, r2, r3;
            upk2(acc[m][i][0], r0, r1);
            upk2(acc[m][i][1], r2, r3);
            float4 v = make_float4((r0 + bs.x) * s, (r1 + bs.y) * s,
                                   (r2 + bs.z) * s, (r3 + bs.w) * s);
            *(float4*)(ob + (size_t)i * CO) = v;
        }
    }
}

// ---------------------------------------------------------------------------
// Fused neighborhood attention — natt_v2, EXACT R10 source (measured 32.2us).
// Two-pass (sc[49]), split score chains, conflict-free lane remap.
// ---------------------------------------------------------------------------
__global__ __launch_bounds__(256, 2) void natt_kernel(float* __restrict__ outp)
{
    extern __shared__ float sm[];
    float* Ks = sm;
    float* Vs = sm + HALO_MAX * PAD;

    const int z    = blockIdx.z;
    const int b    = z >> 2;
    const int parh = (z >> 1) & 1;
    const int parw = z & 1;
    const int ph0  = blockIdx.y * PT;
    const int pw0  = blockIdx.x * PT;
    const int r0p  = max(0, ph0 - 3);
    const int c0p  = max(0, pw0 - 3);
    const int rows = min(HALO, PL - r0p);
    const int cols = min(HALO, PL - c0p);
    const int tid  = threadIdx.x;

    // halo load: 16 threads per loc, float4 each
    {
        const float* kb = g_k + (size_t)b * HW * CO;
        const float* vb = g_v + (size_t)b * HW * CO;
        const int l16 = tid & 15;
        const int nloc = rows * cols;
        for (int loc = tid >> 4; loc < nloc; loc += 16) {
            int lr = loc / cols;
            int lc = loc - lr * cols;
            int h  = 2 * (r0p + lr) + parh;
            int w  = 2 * (c0p + lc) + parw;
            size_t g = ((size_t)h * WWD + w) * CO + l16 * 4;
            int s = loc * PAD + l16 * 4;
            *(float4*)(Ks + s) = *(const float4*)(kb + g);
            *(float4*)(Vs + s) = *(const float4*)(vb + g);
        }
    }
    __syncthreads();

    const int lane = tid & 31;
    const int warp = tid >> 5;        // tile row 0..7
    const int sub  = lane >> 3;       // channel quarter 0..3
    const int pwl  = lane & 7;        // tile col 0..7
    const int ph   = ph0 + warp;
    const int pw   = pw0 + pwl;
    const int h    = 2 * ph + parh;
    const int w    = 2 * pw + parw;

    const float* qp = g_q + ((size_t)b * HW + (size_t)h * WWD + w) * CO + sub * 16;
    ulonglong2 qa = *(const ulonglong2*)(qp);
    ulonglong2 qb_ = *(const ulonglong2*)(qp + 4);
    ulonglong2 qc = *(const ulonglong2*)(qp + 8);
    ulonglong2 qd = *(const ulonglong2*)(qp + 12);
    ull qq[8] = { qa.x, qa.y, qb_.x, qb_.y, qc.x, qc.y, qd.x, qd.y };

    const int wsh = min(max(ph - 3, 0), PL - 7);
    const int wsw = min(max(pw - 3, 0), PL - 7);
    const int rowstride = cols * PAD;
    int rb[7], cb[7];
#pragma unroll
    for (int j = 0; j < 7; j++) {
        rb[j] = (wsh + j - r0p) * rowstride + sub * 16;
        cb[j] = (wsw + j - c0p) * PAD;
    }

    float sc[49];
#pragma unroll
    for (int jh = 0; jh < 7; jh++) {
#pragma unroll
        for (int jw = 0; jw < 7; jw++) {
            const float* kp = Ks + rb[jh] + cb[jw];
            ull s2a = 0ull, s2b = 0ull;
#pragma unroll
            for (int i = 0; i < 4; i++) {
                ulonglong2 kv = *(const ulonglong2*)(kp + i * 4);
                fma2(s2a, qq[2 * i],     kv.x);
                fma2(s2b, qq[2 * i + 1], kv.y);
            }
            float ax, ay, bx, by;
            upk2(s2a, ax, ay);
            upk2(s2b, bx, by);
            float s = (ax + bx) + (ay + by);
            s += __shfl_xor_sync(0xffffffffu, s, 8);
            s += __shfl_xor_sync(0xffffffffu, s, 16);
            sc[jh * 7 + jw] = s;
        }
    }

    float m = sc[0];
#pragma unroll
    for (int j = 1; j < 49; j++) m = fmaxf(m, sc[j]);
    float sum = 0.f;
#pragma unroll
    for (int j = 0; j < 49; j++) { sc[j] = __expf(sc[j] - m); sum += sc[j]; }
    const float inv = 1.0f / sum;

    ull a2[8];
#pragma unroll
    for (int i = 0; i < 8; i++) a2[i] = 0ull;
#pragma unroll
    for (int jh = 0; jh < 7; jh++) {
#pragma unroll
        for (int jw = 0; jw < 7; jw++) {
            float pj = sc[jh * 7 + jw] * inv;
            ull pp = pk2(pj, pj);
            const float* vp = Vs + rb[jh] + cb[jw];
#pragma unroll
            for (int i = 0; i < 4; i++) {
                ulonglong2 vv = *(const ulonglong2*)(vp + i * 4);
                fma2(a2[2 * i],     pp, vv.x);
                fma2(a2[2 * i + 1], pp, vv.y);
            }
        }
    }

    float* ob = outp + ((size_t)b * CO + sub * 16) * HW + (size_t)h * WWD + w;
#pragma unroll
    for (int i = 0; i < 8; i++) {
        float x0, x1;
        upk2(a2[i], x0, x1);
        ob[(size_t)(2 * i) * HW]     = x0;
        ob[(size_t)(2 * i + 1) * HW] = x1;
    }
}

// ---------------------------------------------------------------------------
extern "C" void kernel_launch(void* const* d_in, const int* in_sizes, int n_in,
                              void* d_out, int out_size)
{
    (void)in_sizes; (void)n_in; (void)out_size;
    const float* x  = (const float*)d_in[0];
    const float* Wq = (const float*)d_in[1];
    const float* bq = (const float*)d_in[2];
    const float* Wk = (const float*)d_in[3];
    const float* bk = (const float*)d_in[4];
    const float* Wv = (const float*)d_in[5];
    const float* bv = (const float*)d_in[6];
    float* out = (float*)d_out;

    transposeW<<<96, 256>>>(Wq, Wk, Wv);
    qkv_gemm<<<dim3(98, 2), 512>>>(x, bq, bk, bv);   // 98*128 = 12544 px

    const int smem = 2 * HALO_MAX * PAD * (int)sizeof(float);   // 106624
    cudaFuncSetAttribute(natt_kernel, cudaFuncAttributeMaxDynamicSharedMemorySize, smem);
    natt_kernel<<<dim3(7, 7, 8), 256, smem>>>(out);
}

// round 14
// speedup vs baseline: 1.1590x; 1.1265x over previous
#include <cuda_runtime.h>

#define HH   112
#define WWD  112
#define HW   12544
#define CIN  128
#define CO   64
#define BATCH 2

// parity-space constants: K=7, D=1, L=56
#define PL   56
#define PT   8          // parity tile = 8x8
#define HALO 14         // 8 + 6
#define PAD  68         // floats per loc -> 17 float4 slots
#define HALO_MAX (HALO * HALO)   // 196

// GEMM smem layout (floats, dynamic) — 256-thread / 64-px tile version
#define WS_STRIDE 68
#define WS_MAT    (32 * WS_STRIDE)     // 2176
#define WST_STRIDE 33
#define WST_MAT    (64 * WST_STRIDE)   // 2112
#define OFF_XS   0                      // Xs[32][64] = 2048 floats
#define OFF_WS   2048
#define OFF_WST  (2048 + 3 * WS_MAT)            // 2048 + 6528 = 8576
#define GEMM_SMEM_FLOATS (OFF_WST + 3 * WST_MAT)  // 8576 + 6336 = 14912 (59648 B)

typedef unsigned long long ull;

// scratch
__device__ __align__(128) float g_q[BATCH * HW * CO];
__device__ __align__(128) float g_k[BATCH * HW * CO];
__device__ __align__(128) float g_v[BATCH * HW * CO];

// ---------------------------------------------------------------------------
__device__ __forceinline__ ull pk2(float x, float y) {
    ull r; asm("mov.b64 %0, {%1,%2};" : "=l"(r) : "f"(x), "f"(y)); return r;
}
__device__ __forceinline__ void upk2(ull v, float& x, float& y) {
    asm("mov.b64 {%0,%1}, %2;" : "=f"(x), "=f"(y) : "l"(v));
}
__device__ __forceinline__ void fma2(ull& d, ull a, ull b) {
    asm("fma.rn.f32x2 %0, %1, %2, %3;" : "=l"(d) : "l"(a), "l"(b), "l"(d));
}

// ---------------------------------------------------------------------------
// Fused QKV GEMM with in-kernel staged W transpose.
// Tile 64 px x 64 out x 3 mats, 256 threads, __launch_bounds__(256,2) -> occ 2.
// Per chunk: coalesced LDG of W rows -> Wst (stride 33, bank-clean scalar STS)
// -> column gather (kk lane-fast, bank-clean LDS.32) -> Ws[kk][o] stride 68
// (STS.128 + compute LDS.128 both phase-conflict-free).
// ---------------------------------------------------------------------------
__global__ __launch_bounds__(256, 2) void qkv_gemm(
    const float* __restrict__ x,
    const float* __restrict__ Wq, const float* __restrict__ Wk,
    const float* __restrict__ Wv,
    const float* __restrict__ bq, const float* __restrict__ bk,
    const float* __restrict__ bv)
{
    extern __shared__ float sm[];
    float* Xs  = sm + OFF_XS;
    float* Ws  = sm + OFF_WS;
    float* Wst = sm + OFF_WST;

    const int b   = blockIdx.y;
    const int hw0 = blockIdx.x * 64;
    const int tid = threadIdx.x;
    const int tp  = tid >> 4;             // 0..15 (4 px each)
    const int to  = tid & 15;             // 0..15 (4 out each)

    ull acc[3][4][2];
#pragma unroll
    for (int m = 0; m < 3; m++)
#pragma unroll
        for (int i = 0; i < 4; i++)
#pragma unroll
            for (int j = 0; j < 2; j++) acc[m][i][j] = 0ull;

    const float* xb = x + (size_t)b * CIN * HW + hw0;
    const float* Wsrc[3] = { Wq, Wk, Wv };

    for (int kc = 0; kc < CIN; kc += 32) {
        __syncthreads();
        // Xs: 32 c x 64 px = 512 float4, 2 per thread, coalesced
#pragma unroll
        for (int t = 0; t < 2; t++) {
            int idx = tid + t * 256;       // 0..511
            int c   = idx >> 4;            // 0..31
            int p4  = idx & 15;            // 0..15
            ((float4*)Xs)[c * 16 + p4] =
                *(const float4*)(xb + (size_t)(kc + c) * HW + p4 * 4);
        }
        // Stage A: W[o][kc..kc+31] -> Wst[m][o][j] (stride 33). Coalesced LDG.128,
        // scalar STS banks (o + 4*j4 + i) all-distinct per warp.
#pragma unroll
        for (int t = 0; t < 6; t++) {
            int idx = tid + t * 256;       // 0..1535
            int m   = idx >> 9;
            int rem = idx & 511;
            int o   = rem >> 3;            // 0..63
            int j4  = rem & 7;             // 0..7
            float4 wv = *(const float4*)(Wsrc[m] + (size_t)o * CIN + kc + j4 * 4);
            float* dst = Wst + m * WST_MAT + o * WST_STRIDE + j4 * 4;
            dst[0] = wv.x; dst[1] = wv.y; dst[2] = wv.z; dst[3] = wv.w;
        }
        __syncthreads();
        // Stage B: gather Wst columns -> Ws[m][kk][o] (stride 68).
        // kk = lane -> LDS banks (4*o4 + e + kk) all-distinct; STS.128 slots
        // (17*kk + o4) conflict-free per phase.
#pragma unroll
        for (int t = 0; t < 6; t++) {
            int idx = tid + t * 256;       // 0..1535
            int m   = idx >> 9;
            int rem = idx & 511;
            int o4  = rem >> 5;            // 0..15
            int kk  = rem & 31;            // 0..31
            const float* src = Wst + m * WST_MAT + kk;
            float4 v;
            v.x = src[(o4 * 4 + 0) * WST_STRIDE];
            v.y = src[(o4 * 4 + 1) * WST_STRIDE];
            v.z = src[(o4 * 4 + 2) * WST_STRIDE];
            v.w = src[(o4 * 4 + 3) * WST_STRIDE];
            *(float4*)(Ws + m * WS_MAT + kk * WS_STRIDE + o4 * 4) = v;
        }
        __syncthreads();

#pragma unroll 4
        for (int kk = 0; kk < 32; kk++) {
            float4 af = *(const float4*)(Xs + kk * 64 + tp * 4);
            ull a0 = pk2(af.x, af.x), a1 = pk2(af.y, af.y);
            ull a2_ = pk2(af.z, af.z), a3 = pk2(af.w, af.w);
#pragma unroll
            for (int m = 0; m < 3; m++) {
                ulonglong2 w2 = *(const ulonglong2*)(Ws + m * WS_MAT + kk * WS_STRIDE + to * 4);
                fma2(acc[m][0][0], a0, w2.x);  fma2(acc[m][0][1], a0, w2.y);
                fma2(acc[m][1][0], a1, w2.x);  fma2(acc[m][1][1], a1, w2.y);
                fma2(acc[m][2][0], a2_, w2.x); fma2(acc[m][2][1], a2_, w2.y);
                fma2(acc[m][3][0], a3, w2.x);  fma2(acc[m][3][1], a3, w2.y);
            }
        }
    }

    // epilogue: + bias, * scale, store (b, hw, o) with o contiguous
    const float* biases[3] = { bq, bk, bv };
    float* outs[3] = { g_q, g_k, g_v };
    const float scales[3] = { 0.125f, 1.0f, 1.0f };
#pragma unroll
    for (int m = 0; m < 3; m++) {
        float4 bs = *(const float4*)(biases[m] + to * 4);
        float s = scales[m];
        float* ob = outs[m] + ((size_t)b * HW + hw0 + tp * 4) * CO + to * 4;
#pragma unroll
        for (int i = 0; i < 4; i++) {
            float r0, r1, r2, r3;
            upk2(acc[m][i][0], r0, r1);
            upk2(acc[m][i][1], r2, r3);
            float4 v = make_float4((r0 + bs.x) * s, (r1 + bs.y) * s,
                                   (r2 + bs.z) * s, (r3 + bs.w) * s);
            *(float4*)(ob + (size_t)i * CO) = v;
        }
    }
}

// ---------------------------------------------------------------------------
// Fused neighborhood attention — EXACT R10 version (part of 72.2us best).
// Two-pass (sc[49]), split score chains, conflict-free lane remap.
// ---------------------------------------------------------------------------
__global__ __launch_bounds__(256, 2) void natt_kernel(float* __restrict__ outp)
{
    extern __shared__ float sm[];
    float* Ks = sm;
    float* Vs = sm + HALO_MAX * PAD;

    const int z    = blockIdx.z;
    const int b    = z >> 2;
    const int parh = (z >> 1) & 1;
    const int parw = z & 1;
    const int ph0  = blockIdx.y * PT;
    const int pw0  = blockIdx.x * PT;
    const int r0p  = max(0, ph0 - 3);
    const int c0p  = max(0, pw0 - 3);
    const int rows = min(HALO, PL - r0p);
    const int cols = min(HALO, PL - c0p);
    const int tid  = threadIdx.x;

    // halo load: 16 threads per loc, float4 each
    {
        const float* kb = g_k + (size_t)b * HW * CO;
        const float* vb = g_v + (size_t)b * HW * CO;
        const int l16 = tid & 15;
        const int nloc = rows * cols;
        for (int loc = tid >> 4; loc < nloc; loc += 16) {
            int lr = loc / cols;
            int lc = loc - lr * cols;
            int h  = 2 * (r0p + lr) + parh;
            int w  = 2 * (c0p + lc) + parw;
            size_t g = ((size_t)h * WWD + w) * CO + l16 * 4;
            int s = loc * PAD + l16 * 4;
            *(float4*)(Ks + s) = *(const float4*)(kb + g);
            *(float4*)(Vs + s) = *(const float4*)(vb + g);
        }
    }
    __syncthreads();

    const int lane = tid & 31;
    const int warp = tid >> 5;        // tile row 0..7
    const int sub  = lane >> 3;       // channel quarter 0..3
    const int pwl  = lane & 7;        // tile col 0..7
    const int ph   = ph0 + warp;
    const int pw   = pw0 + pwl;
    const int h    = 2 * ph + parh;
    const int w    = 2 * pw + parw;

    const float* qp = g_q + ((size_t)b * HW + (size_t)h * WWD + w) * CO + sub * 16;
    ulonglong2 qa = *(const ulonglong2*)(qp);
    ulonglong2 qb_ = *(const ulonglong2*)(qp + 4);
    ulonglong2 qc = *(const ulonglong2*)(qp + 8);
    ulonglong2 qd = *(const ulonglong2*)(qp + 12);
    ull qq[8] = { qa.x, qa.y, qb_.x, qb_.y, qc.x, qc.y, qd.x, qd.y };

    const int wsh = min(max(ph - 3, 0), PL - 7);
    const int wsw = min(max(pw - 3, 0), PL - 7);
    const int rowstride = cols * PAD;
    int rb[7], cb[7];
#pragma unroll
    for (int j = 0; j < 7; j++) {
        rb[j] = (wsh + j - r0p) * rowstride + sub * 16;
        cb[j] = (wsw + j - c0p) * PAD;
    }

    float sc[49];
#pragma unroll
    for (int jh = 0; jh < 7; jh++) {
#pragma unroll
        for (int jw = 0; jw < 7; jw++) {
            const float* kp = Ks + rb[jh] + cb[jw];
            ull s2a = 0ull, s2b = 0ull;
#pragma unroll
            for (int i = 0; i < 4; i++) {
                ulonglong2 kv = *(const ulonglong2*)(kp + i * 4);
                fma2(s2a, qq[2 * i],     kv.x);
                fma2(s2b, qq[2 * i + 1], kv.y);
            }
            float ax, ay, bx, by;
            upk2(s2a, ax, ay);
            upk2(s2b, bx, by);
            float s = (ax + bx) + (ay + by);
            s += __shfl_xor_sync(0xffffffffu, s, 8);
            s += __shfl_xor_sync(0xffffffffu, s, 16);
            sc[jh * 7 + jw] = s;
        }
    }

    float m = sc[0];
#pragma unroll
    for (int j = 1; j < 49; j++) m = fmaxf(m, sc[j]);
    float sum = 0.f;
#pragma unroll
    for (int j = 0; j < 49; j++) { sc[j] = __expf(sc[j] - m); sum += sc[j]; }
    const float inv = 1.0f / sum;

    ull a2[8];
#pragma unroll
    for (int i = 0; i < 8; i++) a2[i] = 0ull;
#pragma unroll
    for (int jh = 0; jh < 7; jh++) {
#pragma unroll
        for (int jw = 0; jw < 7; jw++) {
            float pj = sc[jh * 7 + jw] * inv;
            ull pp = pk2(pj, pj);
            const float* vp = Vs + rb[jh] + cb[jw];
#pragma unroll
            for (int i = 0; i < 4; i++) {
                ulonglong2 vv = *(const ulonglong2*)(vp + i * 4);
                fma2(a2[2 * i],     pp, vv.x);
                fma2(a2[2 * i + 1], pp, vv.y);
            }
        }
    }

    float* ob = outp + ((size_t)b * CO + sub * 16) * HW + (size_t)h * WWD + w;
#pragma unroll
    for (int i = 0; i < 8; i++) {
        float x0, x1;
        upk2(a2[i], x0, x1);
        ob[(size_t)(2 * i) * HW]     = x0;
        ob[(size_t)(2 * i + 1) * HW] = x1;
    }
}

// ---------------------------------------------------------------------------
extern "C" void kernel_launch(void* const* d_in, const int* in_sizes, int n_in,
                              void* d_out, int out_size)
{
    (void)in_sizes; (void)n_in; (void)out_size;
    const float* x  = (const float*)d_in[0];
    const float* Wq = (const float*)d_in[1];
    const float* bq = (const float*)d_in[2];
    const float* Wk = (const float*)d_in[3];
    const float* bk = (const float*)d_in[4];
    const float* Wv = (const float*)d_in[5];
    const float* bv = (const float*)d_in[6];
    float* out = (float*)d_out;

    const int gsmem = GEMM_SMEM_FLOATS * (int)sizeof(float);    // 59648
    cudaFuncSetAttribute(qkv_gemm, cudaFuncAttributeMaxDynamicSharedMemorySize, gsmem);
    qkv_gemm<<<dim3(196, 2), 256, gsmem>>>(x, Wq, Wk, Wv, bq, bk, bv);  // 196*64 = 12544 px

    const int smem = 2 * HALO_MAX * PAD * (int)sizeof(float);   // 106624
    cudaFuncSetAttribute(natt_kernel, cudaFuncAttributeMaxDynamicSharedMemorySize, smem);
    natt_kernel<<<dim3(7, 7, 8), 256, smem>>>(out);
}

// round 15
// speedup vs baseline: 1.1961x; 1.0320x over previous
#include <cuda_runtime.h>

#define HH   112
#define WWD  112
#define HW   12544
#define CIN  128
#define CO   64
#define BATCH 2

// parity-space constants: K=7, D=1, L=56
#define PL   56
#define PT   8          // parity tile = 8x8
#define HALO 14         // 8 + 6
#define PAD  68         // floats per loc -> 17 float4 slots
#define HALO_MAX (HALO * HALO)   // 196

// GEMM smem layout (floats, dynamic) — 256-thread / 64-px tile version
#define WS_STRIDE 68
#define WS_MAT    (32 * WS_STRIDE)     // 2176
#define WST_STRIDE 33
#define WST_MAT    (64 * WST_STRIDE)   // 2112
#define OFF_XS   0                      // Xs[32][64] = 2048 floats
#define OFF_WS   2048
#define OFF_WST  (2048 + 3 * WS_MAT)            // 8576
#define GEMM_SMEM_FLOATS (OFF_WST + 3 * WST_MAT)  // 14912 (59648 B)

typedef unsigned long long ull;

// scratch
__device__ __align__(128) float g_q[BATCH * HW * CO];
__device__ __align__(128) float g_k[BATCH * HW * CO];
__device__ __align__(128) float g_v[BATCH * HW * CO];

// ---------------------------------------------------------------------------
__device__ __forceinline__ ull pk2(float x, float y) {
    ull r; asm("mov.b64 %0, {%1,%2};" : "=l"(r) : "f"(x), "f"(y)); return r;
}
__device__ __forceinline__ void upk2(ull v, float& x, float& y) {
    asm("mov.b64 {%0,%1}, %2;" : "=f"(x), "=f"(y) : "l"(v));
}
__device__ __forceinline__ void fma2(ull& d, ull a, ull b) {
    asm("fma.rn.f32x2 %0, %1, %2, %3;" : "=l"(d) : "l"(a), "l"(b), "l"(d));
}

// ---------------------------------------------------------------------------
// Fused QKV GEMM with in-kernel staged W transpose. Tile 64px x 64out x 3,
// 256 threads, occ 2. Thread = 8 px (warp-uniform -> X broadcast) x 2 outs.
// Per kk: 2 X-LDS.128 (broadcast, consumed as px-pair f32x2), 3 W-LDS.64
// (conflict-free), 24 FFMA2. FFMA2 is the only binding pipe.
// ---------------------------------------------------------------------------
__global__ __launch_bounds__(256, 2) void qkv_gemm(
    const float* __restrict__ x,
    const float* __restrict__ Wq, const float* __restrict__ Wk,
    const float* __restrict__ Wv,
    const float* __restrict__ bq, const float* __restrict__ bk,
    const float* __restrict__ bv)
{
    extern __shared__ float sm[];
    float* Xs  = sm + OFF_XS;
    float* Ws  = sm + OFF_WS;
    float* Wst = sm + OFF_WST;

    const int b   = blockIdx.y;
    const int hw0 = blockIdx.x * 64;
    const int tid = threadIdx.x;
    const int tp  = tid >> 5;             // 0..7  (8 px each, warp-uniform)
    const int to2 = tid & 31;             // 0..31 (2 outs each)

    ull acc[3][4][2];                     // [mat][px-pair][out]
#pragma unroll
    for (int m = 0; m < 3; m++)
#pragma unroll
        for (int i = 0; i < 4; i++)
#pragma unroll
            for (int j = 0; j < 2; j++) acc[m][i][j] = 0ull;

    const float* xb = x + (size_t)b * CIN * HW + hw0;
    const float* Wsrc[3] = { Wq, Wk, Wv };

    for (int kc = 0; kc < CIN; kc += 32) {
        __syncthreads();
        // Xs: 32 c x 64 px = 512 float4, 2 per thread, coalesced
#pragma unroll
        for (int t = 0; t < 2; t++) {
            int idx = tid + t * 256;       // 0..511
            int c   = idx >> 4;            // 0..31
            int p4  = idx & 15;            // 0..15
            ((float4*)Xs)[c * 16 + p4] =
                *(const float4*)(xb + (size_t)(kc + c) * HW + p4 * 4);
        }
        // Stage A: W[o][kc..kc+31] -> Wst[m][o][j] (stride 33), bank-clean.
#pragma unroll
        for (int t = 0; t < 6; t++) {
            int idx = tid + t * 256;       // 0..1535
            int m   = idx >> 9;
            int rem = idx & 511;
            int o   = rem >> 3;            // 0..63
            int j4  = rem & 7;             // 0..7
            float4 wv = *(const float4*)(Wsrc[m] + (size_t)o * CIN + kc + j4 * 4);
            float* dst = Wst + m * WST_MAT + o * WST_STRIDE + j4 * 4;
            dst[0] = wv.x; dst[1] = wv.y; dst[2] = wv.z; dst[3] = wv.w;
        }
        __syncthreads();
        // Stage B: gather Wst columns -> Ws[m][kk][o] (stride 68), bank-clean.
#pragma unroll
        for (int t = 0; t < 6; t++) {
            int idx = tid + t * 256;       // 0..1535
            int m   = idx >> 9;
            int rem = idx & 511;
            int o4  = rem >> 5;            // 0..15
            int kk  = rem & 31;            // 0..31
            const float* src = Wst + m * WST_MAT + kk;
            float4 v;
            v.x = src[(o4 * 4 + 0) * WST_STRIDE];
            v.y = src[(o4 * 4 + 1) * WST_STRIDE];
            v.z = src[(o4 * 4 + 2) * WST_STRIDE];
            v.w = src[(o4 * 4 + 3) * WST_STRIDE];
            *(float4*)(Ws + m * WS_MAT + kk * WS_STRIDE + o4 * 4) = v;
        }
        __syncthreads();

#pragma unroll 4
        for (int kk = 0; kk < 32; kk++) {
            // X: warp-uniform broadcast loads, px pairs already packed
            ulonglong2 xa = *(const ulonglong2*)(Xs + kk * 64 + tp * 8);
            ulonglong2 xc = *(const ulonglong2*)(Xs + kk * 64 + tp * 8 + 4);
#pragma unroll
            for (int m = 0; m < 3; m++) {
                float2 wv = *(const float2*)(Ws + m * WS_MAT + kk * WS_STRIDE + to2 * 2);
                ull w0 = pk2(wv.x, wv.x), w1 = pk2(wv.y, wv.y);
                fma2(acc[m][0][0], xa.x, w0); fma2(acc[m][0][1], xa.x, w1);
                fma2(acc[m][1][0], xa.y, w0); fma2(acc[m][1][1], xa.y, w1);
                fma2(acc[m][2][0], xc.x, w0); fma2(acc[m][2][1], xc.x, w1);
                fma2(acc[m][3][0], xc.y, w0); fma2(acc[m][3][1], xc.y, w1);
            }
        }
    }

    // epilogue: + bias, * scale, store (b, hw, o); 8B stores, fully coalesced
    const float* biases[3] = { bq, bk, bv };
    float* outs[3] = { g_q, g_k, g_v };
    const float scales[3] = { 0.125f, 1.0f, 1.0f };
#pragma unroll
    for (int m = 0; m < 3; m++) {
        float2 bs = *(const float2*)(biases[m] + to2 * 2);
        float s = scales[m];
        float* ob = outs[m] + ((size_t)b * HW + hw0 + tp * 8) * CO + to2 * 2;
#pragma unroll
        for (int i = 0; i < 4; i++) {
            float e0, o0, e1, o1;          // even/odd px for out0, out1
            upk2(acc[m][i][0], e0, o0);
            upk2(acc[m][i][1], e1, o1);
            float2 v0 = make_float2((e0 + bs.x) * s, (e1 + bs.y) * s);
            float2 v1 = make_float2((o0 + bs.x) * s, (o1 + bs.y) * s);
            *(float2*)(ob + (size_t)(2 * i) * CO)     = v0;
            *(float2*)(ob + (size_t)(2 * i + 1) * CO) = v1;
        }
    }
}

// ---------------------------------------------------------------------------
// Fused neighborhood attention — EXACT R14 version (part of 66.0us best).
// ---------------------------------------------------------------------------
__global__ __launch_bounds__(256, 2) void natt_kernel(float* __restrict__ outp)
{
    extern __shared__ float sm[];
    float* Ks = sm;
    float* Vs = sm + HALO_MAX * PAD;

    const int z    = blockIdx.z;
    const int b    = z >> 2;
    const int parh = (z >> 1) & 1;
    const int parw = z & 1;
    const int ph0  = blockIdx.y * PT;
    const int pw0  = blockIdx.x * PT;
    const int r0p  = max(0, ph0 - 3);
    const int c0p  = max(0, pw0 - 3);
    const int rows = min(HALO, PL - r0p);
    const int cols = min(HALO, PL - c0p);
    const int tid  = threadIdx.x;

    // halo load: 16 threads per loc, float4 each
    {
        const float* kb = g_k + (size_t)b * HW * CO;
        const float* vb = g_v + (size_t)b * HW * CO;
        const int l16 = tid & 15;
        const int nloc = rows * cols;
        for (int loc = tid >> 4; loc < nloc; loc += 16) {
            int lr = loc / cols;
            int lc = loc - lr * cols;
            int h  = 2 * (r0p + lr) + parh;
            int w  = 2 * (c0p + lc) + parw;
            size_t g = ((size_t)h * WWD + w) * CO + l16 * 4;
            int s = loc * PAD + l16 * 4;
            *(float4*)(Ks + s) = *(const float4*)(kb + g);
            *(float4*)(Vs + s) = *(const float4*)(vb + g);
        }
    }
    __syncthreads();

    const int lane = tid & 31;
    const int warp = tid >> 5;        // tile row 0..7
    const int sub  = lane >> 3;       // channel quarter 0..3
    const int pwl  = lane & 7;        // tile col 0..7
    const int ph   = ph0 + warp;
    const int pw   = pw0 + pwl;
    const int h    = 2 * ph + parh;
    const int w    = 2 * pw + parw;

    const float* qp = g_q + ((size_t)b * HW + (size_t)h * WWD + w) * CO + sub * 16;
    ulonglong2 qa = *(const ulonglong2*)(qp);
    ulonglong2 qb_ = *(const ulonglong2*)(qp + 4);
    ulonglong2 qc = *(const ulonglong2*)(qp + 8);
    ulonglong2 qd = *(const ulonglong2*)(qp + 12);
    ull qq[8] = { qa.x, qa.y, qb_.x, qb_.y, qc.x, qc.y, qd.x, qd.y };

    const int wsh = min(max(ph - 3, 0), PL - 7);
    const int wsw = min(max(pw - 3, 0), PL - 7);
    const int rowstride = cols * PAD;
    int rb[7], cb[7];
#pragma unroll
    for (int j = 0; j < 7; j++) {
        rb[j] = (wsh + j - r0p) * rowstride + sub * 16;
        cb[j] = (wsw + j - c0p) * PAD;
    }

    float sc[49];
#pragma unroll
    for (int jh = 0; jh < 7; jh++) {
#pragma unroll
        for (int jw = 0; jw < 7; jw++) {
            const float* kp = Ks + rb[jh] + cb[jw];
            ull s2a = 0ull, s2b = 0ull;
#pragma unroll
            for (int i = 0; i < 4; i++) {
                ulonglong2 kv = *(const ulonglong2*)(kp + i * 4);
                fma2(s2a, qq[2 * i],     kv.x);
                fma2(s2b, qq[2 * i + 1], kv.y);
            }
            float ax, ay, bx, by;
            upk2(s2a, ax, ay);
            upk2(s2b, bx, by);
            float s = (ax + bx) + (ay + by);
            s += __shfl_xor_sync(0xffffffffu, s, 8);
            s += __shfl_xor_sync(0xffffffffu, s, 16);
            sc[jh * 7 + jw] = s;
        }
    }

    float m = sc[0];
#pragma unroll
    for (int j = 1; j < 49; j++) m = fmaxf(m, sc[j]);
    float sum = 0.f;
#pragma unroll
    for (int j = 0; j < 49; j++) { sc[j] = __expf(sc[j] - m); sum += sc[j]; }
    const float inv = 1.0f / sum;

    ull a2[8];
#pragma unroll
    for (int i = 0; i < 8; i++) a2[i] = 0ull;
#pragma unroll
    for (int jh = 0; jh < 7; jh++) {
#pragma unroll
        for (int jw = 0; jw < 7; jw++) {
            float pj = sc[jh * 7 + jw] * inv;
            ull pp = pk2(pj, pj);
            const float* vp = Vs + rb[jh] + cb[jw];
#pragma unroll
            for (int i = 0; i < 4; i++) {
                ulonglong2 vv = *(const ulonglong2*)(vp + i * 4);
                fma2(a2[2 * i],     pp, vv.x);
                fma2(a2[2 * i + 1], pp, vv.y);
            }
        }
    }

    float* ob = outp + ((size_t)b * CO + sub * 16) * HW + (size_t)h * WWD + w;
#pragma unroll
    for (int i = 0; i < 8; i++) {
        float x0, x1;
        upk2(a2[i], x0, x1);
        ob[(size_t)(2 * i) * HW]     = x0;
        ob[(size_t)(2 * i + 1) * HW] = x1;
    }
}

// ---------------------------------------------------------------------------
extern "C" void kernel_launch(void* const* d_in, const int* in_sizes, int n_in,
                              void* d_out, int out_size)
{
    (void)in_sizes; (void)n_in; (void)out_size;
    const float* x  = (const float*)d_in[0];
    const float* Wq = (const float*)d_in[1];
    const float* bq = (const float*)d_in[2];
    const float* Wk = (const float*)d_in[3];
    const float* bk = (const float*)d_in[4];
    const float* Wv = (const float*)d_in[5];
    const float* bv = (const float*)d_in[6];
    float* out = (float*)d_out;

    const int gsmem = GEMM_SMEM_FLOATS * (int)sizeof(float);    // 59648
    cudaFuncSetAttribute(qkv_gemm, cudaFuncAttributeMaxDynamicSharedMemorySize, gsmem);
    qkv_gemm<<<dim3(196, 2), 256, gsmem>>>(x, Wq, Wk, Wv, bq, bk, bv);  // 196*64 = 12544 px

    const int smem = 2 * HALO_MAX * PAD * (int)sizeof(float);   // 106624
    cudaFuncSetAttribute(natt_kernel, cudaFuncAttributeMaxDynamicSharedMemorySize, smem);
    natt_kernel<<<dim3(7, 7, 8), 256, smem>>>(out);
}